// round 1
// baseline (speedup 1.0000x reference)
#include <cuda_runtime.h>
#include <math_constants.h>

// Problem constants
#define Bk 2
#define Lk 2048
#define Sk 2048
#define Hk 8
#define Ek 64
#define Dk 64
#define NBH (Bk*Hk)

// Tiling
#define TQ 64
#define TS 128
#define NTHREADS 256

// Padded smem row strides (floats) to avoid bank conflicts
#define QP 65
#define KP 66
#define VP 64
#define PP 68

#define SMEM_FLOATS (TQ*QP + TS*KP + TS*VP + TS*PP)
#define SMEM_BYTES  (SMEM_FLOATS * 4)

// Scratch (static device globals: no runtime allocation allowed)
__device__ float g_Otmp[(size_t)NBH * Lk * Dk];   // [bh][l][d]
__device__ float g_Msp[NBH * Lk];                 // [bh][l]

// ---------------------------------------------------------------------------
// Kernel 1: fused flash attention + sparsity-measure stats.
// One CTA = (b,h) pair x 64-query tile. 256 threads = 16x16 logical grid:
//   tq = tid/16 owns query rows 4*tq..4*tq+3
//   ts = tid%16 owns score cols s = ts + 16k (k<8) in GEMM1, d cols 4*ts.. in GEMM2
// ---------------------------------------------------------------------------
__global__ __launch_bounds__(NTHREADS, 1)
void k_attn(const float* __restrict__ Qg,
            const float* __restrict__ Kg,
            const float* __restrict__ Vg)
{
    extern __shared__ float smem[];
    float* sQ = smem;               // [TQ][QP]
    float* sK = sQ + TQ*QP;         // [TS][KP]
    float* sV = sK + TS*KP;         // [TS][VP]
    float* sP = sV + TS*VP;         // [TS][PP]  P[s][q]

    const int tile = blockIdx.x & 31;      // 32 tiles per (b,h)
    const int bh   = blockIdx.x >> 5;
    const int b = bh >> 3, h = bh & 7;
    const int q0 = tile * TQ;
    const int tid = threadIdx.x;
    const int tq = tid >> 4;
    const int ts = tid & 15;

    const float* Qbase = Qg + ((b*Lk + q0) * Hk + h) * Ek;
    const float* Kbase = Kg + (b*Sk*Hk + h) * Ek;
    const float* Vbase = Vg + (b*Sk*Hk + h) * Dk;

    // Load Q tile (64 rows x 64 floats)
    #pragma unroll
    for (int i = 0; i < 4; i++) {
        int idx = tid + i * NTHREADS;
        int r = idx >> 4, c = (idx & 15) * 4;
        float4 v4 = *(const float4*)(Qbase + r * (Hk*Ek) + c);
        sQ[r*QP + c + 0] = v4.x; sQ[r*QP + c + 1] = v4.y;
        sQ[r*QP + c + 2] = v4.z; sQ[r*QP + c + 3] = v4.w;
    }

    float acc[4][4];
    float m[4], den[4], rsum[4];
    #pragma unroll
    for (int i = 0; i < 4; i++) {
        m[i] = -CUDART_INF_F; den[i] = 0.f; rsum[i] = 0.f;
        #pragma unroll
        for (int j = 0; j < 4; j++) acc[i][j] = 0.f;
    }

    for (int s0 = 0; s0 < Sk; s0 += TS) {
        __syncthreads();   // previous chunk's GEMM2 done before overwriting K/V
        // Load K,V chunk (128 rows x 64 floats each)
        #pragma unroll
        for (int i = 0; i < 8; i++) {
            int idx = tid + i * NTHREADS;
            int r = idx >> 4, c = (idx & 15) * 4;
            float4 kv = *(const float4*)(Kbase + (s0 + r) * (Hk*Ek) + c);
            sK[r*KP + c + 0] = kv.x; sK[r*KP + c + 1] = kv.y;
            sK[r*KP + c + 2] = kv.z; sK[r*KP + c + 3] = kv.w;
            float4 vv = *(const float4*)(Vbase + (s0 + r) * (Hk*Dk) + c);
            *(float4*)(sV + r*VP + c) = vv;
        }
        __syncthreads();

        // GEMM1: raw scores sc[i][k] for (q = 4tq+i, s = ts+16k)
        float sc[4][8];
        #pragma unroll
        for (int i = 0; i < 4; i++)
            #pragma unroll
            for (int k = 0; k < 8; k++) sc[i][k] = 0.f;

        #pragma unroll 4
        for (int e = 0; e < Ek; e++) {
            float qv[4];
            #pragma unroll
            for (int i = 0; i < 4; i++) qv[i] = sQ[(4*tq + i)*QP + e];
            #pragma unroll
            for (int k = 0; k < 8; k++) {
                float kv = sK[(ts + 16*k)*KP + e];
                #pragma unroll
                for (int i = 0; i < 4; i++) sc[i][k] = fmaf(qv[i], kv, sc[i][k]);
            }
        }

        // Per-row stats + online softmax update. Row group = 16 ts lanes
        // within one half-warp; xor offsets < 16 stay inside the half.
        #pragma unroll
        for (int i = 0; i < 4; i++) {
            float cmax = sc[i][0];
            float csum = sc[i][0];
            #pragma unroll
            for (int k = 1; k < 8; k++) { cmax = fmaxf(cmax, sc[i][k]); csum += sc[i][k]; }
            #pragma unroll
            for (int o = 1; o < 16; o <<= 1) {
                cmax = fmaxf(cmax, __shfl_xor_sync(0xffffffffu, cmax, o));
                csum += __shfl_xor_sync(0xffffffffu, csum, o);
            }
            rsum[i] += csum;
            float mnew  = fmaxf(m[i], cmax);
            float scale = __expf((m[i] - mnew) * 0.125f);   // 1/sqrt(64)=0.125 exact
            den[i] *= scale;
            #pragma unroll
            for (int j = 0; j < 4; j++) acc[i][j] *= scale;
            m[i] = mnew;

            float psum = 0.f;
            #pragma unroll
            for (int k = 0; k < 8; k++) {
                float p = __expf((sc[i][k] - mnew) * 0.125f);
                psum += p;
                sP[(ts + 16*k)*PP + 4*tq + i] = p;
            }
            #pragma unroll
            for (int o = 1; o < 16; o <<= 1)
                psum += __shfl_xor_sync(0xffffffffu, psum, o);
            den[i] += psum;
        }
        __syncthreads();

        // GEMM2: acc[i][j] += sum_s P[s][4tq+i] * V[s][4ts+j]
        #pragma unroll 4
        for (int s = 0; s < TS; s++) {
            float4 pv = *(const float4*)(sP + s*PP + 4*tq);
            float4 vv = *(const float4*)(sV + s*VP + 4*ts);
            acc[0][0] = fmaf(pv.x, vv.x, acc[0][0]);
            acc[0][1] = fmaf(pv.x, vv.y, acc[0][1]);
            acc[0][2] = fmaf(pv.x, vv.z, acc[0][2]);
            acc[0][3] = fmaf(pv.x, vv.w, acc[0][3]);
            acc[1][0] = fmaf(pv.y, vv.x, acc[1][0]);
            acc[1][1] = fmaf(pv.y, vv.y, acc[1][1]);
            acc[1][2] = fmaf(pv.y, vv.z, acc[1][2]);
            acc[1][3] = fmaf(pv.y, vv.w, acc[1][3]);
            acc[2][0] = fmaf(pv.z, vv.x, acc[2][0]);
            acc[2][1] = fmaf(pv.z, vv.y, acc[2][1]);
            acc[2][2] = fmaf(pv.z, vv.z, acc[2][2]);
            acc[2][3] = fmaf(pv.z, vv.w, acc[2][3]);
            acc[3][0] = fmaf(pv.w, vv.x, acc[3][0]);
            acc[3][1] = fmaf(pv.w, vv.y, acc[3][1]);
            acc[3][2] = fmaf(pv.w, vv.z, acc[3][2]);
            acc[3][3] = fmaf(pv.w, vv.w, acc[3][3]);
        }
    }

    // Epilogue: normalized output rows + M_sp
    float* Obase = g_Otmp + ((size_t)bh * Lk + q0) * Dk;
    #pragma unroll
    for (int i = 0; i < 4; i++) {
        float inv = 1.0f / den[i];
        float4 o4;
        o4.x = acc[i][0] * inv; o4.y = acc[i][1] * inv;
        o4.z = acc[i][2] * inv; o4.w = acc[i][3] * inv;
        *(float4*)(Obase + (4*tq + i)*Dk + 4*ts) = o4;
    }
    if (ts == 0) {
        #pragma unroll
        for (int i = 0; i < 4; i++)
            g_Msp[bh*Lk + q0 + 4*tq + i] = m[i] - rsum[i] * (1.0f / (float)Sk);
    }
}

// ---------------------------------------------------------------------------
// Kernel 2: per-(b,h) descending rank of M_sp (stable: ties -> lower index
// first, matching jax.lax.top_k) + scatter rows into final output layout.
// ---------------------------------------------------------------------------
__global__ __launch_bounds__(256)
void k_rank_scatter(float* __restrict__ out)
{
    __shared__ float sM[Lk];
    __shared__ int   sR[Lk];
    const int bh = blockIdx.x;
    const int b = bh >> 3, h = bh & 7;
    const int t = threadIdx.x;

    for (int i = t; i < Lk; i += 256) sM[i] = g_Msp[bh*Lk + i];
    __syncthreads();

    // Each thread ranks 8 rows; single pass over the 2048 keys.
    int   li[8];
    float mi[8];
    int   cnt[8];
    #pragma unroll
    for (int r = 0; r < 8; r++) {
        li[r] = t + 256*r;
        mi[r] = sM[li[r]];
        cnt[r] = 0;
    }
    for (int j = 0; j < Lk; j++) {
        float mj = sM[j];
        #pragma unroll
        for (int r = 0; r < 8; r++)
            cnt[r] += (mj > mi[r]) || (mj == mi[r] && j < li[r]);
    }
    #pragma unroll
    for (int r = 0; r < 8; r++) sR[li[r]] = cnt[r];
    __syncthreads();

    // Scatter: out[b, rank(l), h, :] = Otmp[bh, l, :]
    const float* src = g_Otmp + (size_t)bh * Lk * Dk;
    for (int w = t; w < Lk * (Dk/4); w += 256) {
        int l  = w >> 4;
        int c  = (w & 15) * 4;
        float4 v = *(const float4*)(src + l*Dk + c);
        int rr = sR[l];
        *(float4*)(out + (((size_t)b*Lk + rr)*Hk + h)*Dk + c) = v;
    }
}

// ---------------------------------------------------------------------------
extern "C" void kernel_launch(void* const* d_in, const int* in_sizes, int n_in,
                              void* d_out, int out_size)
{
    (void)in_sizes; (void)n_in; (void)out_size;
    const float* Q = (const float*)d_in[0];
    const float* K = (const float*)d_in[1];
    const float* V = (const float*)d_in[2];
    float* out = (float*)d_out;

    cudaFuncSetAttribute(k_attn, cudaFuncAttributeMaxDynamicSharedMemorySize, SMEM_BYTES);

    k_attn<<<NBH * (Lk / TQ), NTHREADS, SMEM_BYTES>>>(Q, K, V);
    k_rank_scatter<<<NBH, 256>>>(out);
}

// round 2
// speedup vs baseline: 1.8297x; 1.8297x over previous
#include <cuda_runtime.h>
#include <math_constants.h>

// Problem constants
#define Bk 2
#define Lk 2048
#define Sk 2048
#define Hk 8
#define Ek 64
#define Dk 64
#define NBH (Bk*Hk)

// Tiling
#define TQ 64
#define TS 128
#define NTHREADS 256

// Padded smem row strides (floats) to avoid bank conflicts
#define QP 65
#define KP 65   // stride 65 mod 32 = 1 -> conflict-free scalar K loads in GEMM1
#define VP 64
#define PP 68

#define SMEM_FLOATS (TQ*QP + TS*KP + TS*VP + TS*PP)
#define SMEM_BYTES  (SMEM_FLOATS * 4)

// Scratch (static device globals: no runtime allocation allowed)
__device__ float g_Otmp[(size_t)NBH * Lk * Dk];            // [bh][l][d]
__device__ unsigned long long g_Key[NBH * Lk];             // packed sort key

// ---------------------------------------------------------------------------
// Kernel 1: fused flash attention + sparsity-measure stats.
// One CTA = (b,h) pair x 64-query tile. 256 threads = 16x16 logical grid:
//   tq = tid/16 owns query rows 4*tq..4*tq+3
//   ts = tid%16 owns score cols s = ts + 16k (k<8) in GEMM1, d cols 4*ts.. in GEMM2
// ---------------------------------------------------------------------------
__global__ __launch_bounds__(NTHREADS, 1)
void k_attn(const float* __restrict__ Qg,
            const float* __restrict__ Kg,
            const float* __restrict__ Vg)
{
    extern __shared__ float smem[];
    float* sQ = smem;               // [TQ][QP]
    float* sK = sQ + TQ*QP;         // [TS][KP]
    float* sV = sK + TS*KP;         // [TS][VP]
    float* sP = sV + TS*VP;         // [TS][PP]  P[s][q]

    const int tile = blockIdx.x & 31;      // 32 tiles per (b,h)
    const int bh   = blockIdx.x >> 5;
    const int b = bh >> 3, h = bh & 7;
    const int q0 = tile * TQ;
    const int tid = threadIdx.x;
    const int tq = tid >> 4;
    const int ts = tid & 15;

    const float* Qbase = Qg + ((b*Lk + q0) * Hk + h) * Ek;
    const float* Kbase = Kg + (b*Sk*Hk + h) * Ek;
    const float* Vbase = Vg + (b*Sk*Hk + h) * Dk;

    // Load Q tile (64 rows x 64 floats)
    #pragma unroll
    for (int i = 0; i < 4; i++) {
        int idx = tid + i * NTHREADS;
        int r = idx >> 4, c = (idx & 15) * 4;
        float4 v4 = *(const float4*)(Qbase + r * (Hk*Ek) + c);
        sQ[r*QP + c + 0] = v4.x; sQ[r*QP + c + 1] = v4.y;
        sQ[r*QP + c + 2] = v4.z; sQ[r*QP + c + 3] = v4.w;
    }

    float acc[4][4];
    float m[4], den[4], rsum[4];
    #pragma unroll
    for (int i = 0; i < 4; i++) {
        m[i] = -CUDART_INF_F; den[i] = 0.f; rsum[i] = 0.f;
        #pragma unroll
        for (int j = 0; j < 4; j++) acc[i][j] = 0.f;
    }

    for (int s0 = 0; s0 < Sk; s0 += TS) {
        __syncthreads();   // previous chunk's GEMM2 done before overwriting K/V
        // Load K,V chunk (128 rows x 64 floats each)
        #pragma unroll
        for (int i = 0; i < 8; i++) {
            int idx = tid + i * NTHREADS;
            int r = idx >> 4, c = (idx & 15) * 4;
            float4 kv = *(const float4*)(Kbase + (s0 + r) * (Hk*Ek) + c);
            sK[r*KP + c + 0] = kv.x; sK[r*KP + c + 1] = kv.y;
            sK[r*KP + c + 2] = kv.z; sK[r*KP + c + 3] = kv.w;
            float4 vv = *(const float4*)(Vbase + (s0 + r) * (Hk*Dk) + c);
            *(float4*)(sV + r*VP + c) = vv;
        }
        __syncthreads();

        // GEMM1: raw scores sc[i][k] for (q = 4tq+i, s = ts+16k)
        float sc[4][8];
        #pragma unroll
        for (int i = 0; i < 4; i++)
            #pragma unroll
            for (int k = 0; k < 8; k++) sc[i][k] = 0.f;

        #pragma unroll 4
        for (int e = 0; e < Ek; e++) {
            float qv[4];
            #pragma unroll
            for (int i = 0; i < 4; i++) qv[i] = sQ[(4*tq + i)*QP + e];
            #pragma unroll
            for (int k = 0; k < 8; k++) {
                float kv = sK[(ts + 16*k)*KP + e];
                #pragma unroll
                for (int i = 0; i < 4; i++) sc[i][k] = fmaf(qv[i], kv, sc[i][k]);
            }
        }

        // Per-row stats + online softmax update. Row group = 16 ts lanes
        // within one half-warp; xor offsets < 16 stay inside the half.
        #pragma unroll
        for (int i = 0; i < 4; i++) {
            float cmax = sc[i][0];
            float csum = sc[i][0];
            #pragma unroll
            for (int k = 1; k < 8; k++) { cmax = fmaxf(cmax, sc[i][k]); csum += sc[i][k]; }
            #pragma unroll
            for (int o = 1; o < 16; o <<= 1) {
                cmax = fmaxf(cmax, __shfl_xor_sync(0xffffffffu, cmax, o));
                csum += __shfl_xor_sync(0xffffffffu, csum, o);
            }
            rsum[i] += csum;
            float mnew  = fmaxf(m[i], cmax);
            float scale = __expf((m[i] - mnew) * 0.125f);   // 1/sqrt(64)=0.125 exact
            den[i] *= scale;
            #pragma unroll
            for (int j = 0; j < 4; j++) acc[i][j] *= scale;
            m[i] = mnew;

            float psum = 0.f;
            #pragma unroll
            for (int k = 0; k < 8; k++) {
                float p = __expf((sc[i][k] - mnew) * 0.125f);
                psum += p;
                sP[(ts + 16*k)*PP + 4*tq + i] = p;
            }
            #pragma unroll
            for (int o = 1; o < 16; o <<= 1)
                psum += __shfl_xor_sync(0xffffffffu, psum, o);
            den[i] += psum;
        }
        __syncthreads();

        // GEMM2: acc[i][j] += sum_s P[s][4tq+i] * V[s][4ts+j]
        #pragma unroll 4
        for (int s = 0; s < TS; s++) {
            float4 pv = *(const float4*)(sP + s*PP + 4*tq);
            float4 vv = *(const float4*)(sV + s*VP + 4*ts);
            acc[0][0] = fmaf(pv.x, vv.x, acc[0][0]);
            acc[0][1] = fmaf(pv.x, vv.y, acc[0][1]);
            acc[0][2] = fmaf(pv.x, vv.z, acc[0][2]);
            acc[0][3] = fmaf(pv.x, vv.w, acc[0][3]);
            acc[1][0] = fmaf(pv.y, vv.x, acc[1][0]);
            acc[1][1] = fmaf(pv.y, vv.y, acc[1][1]);
            acc[1][2] = fmaf(pv.y, vv.z, acc[1][2]);
            acc[1][3] = fmaf(pv.y, vv.w, acc[1][3]);
            acc[2][0] = fmaf(pv.z, vv.x, acc[2][0]);
            acc[2][1] = fmaf(pv.z, vv.y, acc[2][1]);
            acc[2][2] = fmaf(pv.z, vv.z, acc[2][2]);
            acc[2][3] = fmaf(pv.z, vv.w, acc[2][3]);
            acc[3][0] = fmaf(pv.w, vv.x, acc[3][0]);
            acc[3][1] = fmaf(pv.w, vv.y, acc[3][1]);
            acc[3][2] = fmaf(pv.w, vv.z, acc[3][2]);
            acc[3][3] = fmaf(pv.w, vv.w, acc[3][3]);
        }
    }

    // Epilogue: normalized output rows + packed rank key
    float* Obase = g_Otmp + ((size_t)bh * Lk + q0) * Dk;
    #pragma unroll
    for (int i = 0; i < 4; i++) {
        float inv = 1.0f / den[i];
        float4 o4;
        o4.x = acc[i][0] * inv; o4.y = acc[i][1] * inv;
        o4.z = acc[i][2] * inv; o4.w = acc[i][3] * inv;
        *(float4*)(Obase + (4*tq + i)*Dk + 4*ts) = o4;
    }
    if (ts == 0) {
        #pragma unroll
        for (int i = 0; i < 4; i++) {
            float msp = m[i] - rsum[i] * (1.0f / (float)Sk);
            int bi = __float_as_int(msp);
            unsigned u = (unsigned)bi ^ ((bi < 0) ? 0xFFFFFFFFu : 0x80000000u);
            int l = q0 + 4*tq + i;
            // key order: larger M_sp first; ties -> lower index first (~l larger)
            g_Key[bh*Lk + l] =
                ((unsigned long long)u << 32) | (unsigned)(~l);
        }
    }
}

// ---------------------------------------------------------------------------
// Kernel 2: rank via counting on packed u64 keys + fused scatter.
// grid = NBH * 8 blocks; each block owns 256 consecutive rows of one (b,h).
// ---------------------------------------------------------------------------
#define RROWS 256
__global__ __launch_bounds__(256)
void k_rank_scatter(float* __restrict__ out)
{
    __shared__ unsigned long long sKey[Lk];
    __shared__ int sR[RROWS];
    const int slice = blockIdx.x & 7;       // 8 slices per (b,h)
    const int bh    = blockIdx.x >> 3;
    const int b = bh >> 3, h = bh & 7;
    const int t = threadIdx.x;
    const int base = slice * RROWS;

    for (int i = t; i < Lk; i += 256)
        sKey[i] = g_Key[bh*Lk + i];
    __syncthreads();

    // Each thread ranks exactly one row (base + t) against all 2048 keys.
    const unsigned long long my = sKey[base + t];
    int cnt = 0;
    #pragma unroll 8
    for (int j = 0; j < Lk; j++)
        cnt += (sKey[j] > my);
    sR[t] = cnt;
    __syncthreads();

    // Scatter this block's 256 rows: out[b, rank(l), h, :] = Otmp[bh, l, :]
    const float* src = g_Otmp + ((size_t)bh * Lk + base) * Dk;
    for (int w = t; w < RROWS * (Dk/4); w += 256) {
        int lr = w >> 4;                 // local row 0..255
        int c  = (w & 15) * 4;
        float4 v = *(const float4*)(src + lr*Dk + c);
        int rr = sR[lr];
        *(float4*)(out + (((size_t)b*Lk + rr)*Hk + h)*Dk + c) = v;
    }
}

// ---------------------------------------------------------------------------
extern "C" void kernel_launch(void* const* d_in, const int* in_sizes, int n_in,
                              void* d_out, int out_size)
{
    (void)in_sizes; (void)n_in; (void)out_size;
    const float* Q = (const float*)d_in[0];
    const float* K = (const float*)d_in[1];
    const float* V = (const float*)d_in[2];
    float* out = (float*)d_out;

    cudaFuncSetAttribute(k_attn, cudaFuncAttributeMaxDynamicSharedMemorySize, SMEM_BYTES);

    k_attn<<<NBH * (Lk / TQ), NTHREADS, SMEM_BYTES>>>(Q, K, V);
    k_rank_scatter<<<NBH * 8, 256>>>(out);
}